// round 11
// baseline (speedup 1.0000x reference)
#include <cuda_runtime.h>
#include <math.h>

#define Bdim   8
#define Cdim   3
#define Ndim   4096
#define DK     100
#define Kn     20
#define EPSf   1e-5f
#define SLOPEf 0.2f
#define NPTS   (Bdim * Ndim)   // 32768
#define CAP    512             // candidate buffer size

// ---------------- scratch (static device globals; no allocs) ----------------
__device__ float  g_xx[NPTS];             // per-point sum of squares (exact ref formula)
__device__ float  g_mpre[NPTS * 64];      // [b][n][o]  (o contiguous)
__device__ int    g_idxfull[NPTS * DK];   // top-100 neighbor indices per point
__device__ int    g_idxsel[NPTS * Kn];    // dilated 20 neighbor indices
__device__ float  g_hmax[NPTS * 64];      // per (point,o) max_k of h_pre
__device__ float  g_hmin[NPTS * 64];      // per (point,o) min_k of h_pre
__device__ double g_sum1[64], g_sq1[64];
__device__ float  g_sum2f[64], g_sq2f[64];
__device__ float  g_ssumf[Bdim * 64];     // per (b,o) sum of h over n
__device__ float  g_gate[Bdim * 64];      // SE gate s[b][o]
__device__ float  g_dummy[32];            // sink for profiler-alignment dummies

// ---------------- helpers ----------------
__device__ __forceinline__ unsigned f2o(float f) {
    unsigned u = __float_as_uint(f);
    return u ^ ((u & 0x80000000u) ? 0xFFFFFFFFu : 0x80000000u);
}
__device__ __forceinline__ float o2f(unsigned u) {
    unsigned v = u ^ ((u & 0x80000000u) ? 0x80000000u : 0xFFFFFFFFu);
    return __uint_as_float(v);
}
__device__ __forceinline__ float lrelu_exact(float v) {
    return v >= 0.0f ? v : __fmul_rn(SLOPEf, v);
}
// faithful BN apply: ((x - mean) * rstd) * gamma + beta, each op rounded separately
__device__ __forceinline__ float bn_apply(float x, float mean, float rstd, float gamma, float beta) {
    float xn = __fmul_rn(__fsub_rn(x, mean), rstd);
    return __fadd_rn(__fmul_rn(xn, gamma), beta);
}
// warp-level bitonic sort of one value per lane; desc=true -> lane0 largest
__device__ __forceinline__ unsigned warp_sort32(unsigned v, unsigned lane, bool desc) {
    #pragma unroll
    for (unsigned k = 2; k <= 32; k <<= 1) {
        #pragma unroll
        for (unsigned j = k >> 1; j > 0; j >>= 1) {
            unsigned o = __shfl_xor_sync(0xFFFFFFFFu, v, j);
            bool blockdesc = ((lane & k) == 0) == desc;
            bool keepmax = (blockdesc == ((lane & j) == 0));
            unsigned mx = v > o ? v : o, mn = v > o ? o : v;
            v = keepmax ? mx : mn;
        }
    }
    return v;
}

// ---------------- K0: precompute xx (exact ref op order) + zero accumulators ----------------
__global__ __launch_bounds__(512) void pre_kernel(const float* __restrict__ x) {
    int t = blockIdx.x * blockDim.x + threadIdx.x;   // 64 x 512 = 32768
    if (blockIdx.x == 0) {
        if (threadIdx.x < 64) {
            g_sum1[threadIdx.x] = 0.0; g_sq1[threadIdx.x] = 0.0;
            g_sum2f[threadIdx.x] = 0.f; g_sq2f[threadIdx.x] = 0.f;
        }
        if (threadIdx.x < Bdim * 64) g_ssumf[threadIdx.x] = 0.f;
    }
    int b = t >> 12, j = t & (Ndim - 1);
    const float* xb = x + (size_t)b * 3 * Ndim;
    float a0 = xb[j], a1 = xb[Ndim + j], a2 = xb[2 * Ndim + j];
    g_xx[t] = __fadd_rn(__fadd_rn(__fmul_rn(a0, a0), __fmul_rn(a1, a1)),
                        __fmul_rn(a2, a2));
}

// ---------------- dummy: profiler-window alignment (deterministic, trivial) ----------------
__global__ void dummy_kernel(int tag) {
    if (threadIdx.x < 32) g_dummy[threadIdx.x] = (float)tag;
}

// ---------------- K1: per-row exact top-100: warp-sample pivot + rank-by-count ----------------
__global__ __launch_bounds__(256) void topk_kernel(const float* __restrict__ x,
                                                   const float* __restrict__ W_op1) {
    __shared__ unsigned           s_samp[256];     // 1 KB
    __shared__ unsigned long long s_buf[CAP];      // 4 KB
    __shared__ float              s_met[DK];
    __shared__ int                s_cnt;
    __shared__ int                s_count;
    __shared__ int                s_wcnt[8];

    const int p   = blockIdx.x;
    const int b   = p >> 12;
    const int tid = threadIdx.x;
    const unsigned lane = tid & 31, wid = tid >> 5;
    const float* xb = x + (size_t)b * 3 * Ndim;
    const float* gx = g_xx + ((size_t)b << 12);

    const int ii = p & (Ndim - 1);
    const float xi0 = xb[ii], xi1 = xb[Ndim + ii], xi2 = xb[2 * Ndim + ii];
    const float xxi = gx[ii];

    // distances -> 16 register keys per thread (j = it*256 + tid, coalesced)
    unsigned key[16];
    #pragma unroll
    for (int it = 0; it < 16; ++it) {
        int j = it * 256 + tid;
        float a0 = xb[j], a1 = xb[Ndim + j], a2 = xb[2 * Ndim + j];
        float inn = __fmul_rn(xi0, a0);
        inn = __fmaf_rn(xi1, a1, inn);
        inn = __fmaf_rn(xi2, a2, inn);
        float pw = __fsub_rn(__fsub_rn(__fmul_rn(2.0f, inn), xxi), gx[j]);
        key[it] = f2o(pw);
    }
    if (tid == 0) s_cnt = 0;

    // each warp shuffle-sorts its 32 samples (key[0]) descending; no barriers
    s_samp[wid * 32 + lane] = warp_sort32(key[0], lane, true);
    __syncthreads();

    // warp 0 merges the 8 per-warp top-8s (64 values) -> sorted top-32 into s_samp[0..31]
    if (wid == 0) {
        unsigned v0 = s_samp[(lane >> 3) * 32 + (lane & 7)];         // warps 0-3 top8
        unsigned v1 = s_samp[((lane >> 3) + 4) * 32 + (lane & 7)];   // warps 4-7 top8
        v0 = warp_sort32(v0, lane, true);    // descending
        v1 = warp_sort32(v1, lane, false);   // ascending
        unsigned mx = v0 > v1 ? v0 : v1;     // top-32 of 64, bitonic
        #pragma unroll
        for (unsigned j = 16; j > 0; j >>= 1) {
            unsigned o = __shfl_xor_sync(0xFFFFFFFFu, mx, j);
            bool keepmax = ((lane & j) == 0);
            unsigned a = mx > o ? mx : o, c = mx > o ? o : mx;
            mx = keepmax ? a : c;
        }
        s_samp[lane] = mx;
    }
    __syncthreads();

    // collective count of keys >= piv (R6 two-barrier version)
    #define BLK_COUNT(piv)                                                    \
        {                                                                     \
            int c_ = 0;                                                       \
            _Pragma("unroll")                                                 \
            for (int it_ = 0; it_ < 16; ++it_) c_ += (key[it_] >= (piv));     \
            _Pragma("unroll")                                                 \
            for (int off_ = 16; off_ > 0; off_ >>= 1)                         \
                c_ += __shfl_xor_sync(0xFFFFFFFFu, c_, off_);                 \
            if (lane == 0) s_wcnt[wid] = c_;                                  \
            __syncthreads();                                                  \
            if (tid == 0) {                                                   \
                int t_ = 0;                                                   \
                _Pragma("unroll")                                             \
                for (int w_ = 0; w_ < 8; ++w_) t_ += s_wcnt[w_];              \
                s_count = t_;                                                 \
            }                                                                 \
            __syncthreads();                                                  \
        }

    // pivot search: sample-guided, then keyspace binary-search fallback
    unsigned pivot = 0;
    int count = 0;
    bool ok = false;
    int r = 8;
    for (int att = 0; att < 4 && !ok; ++att) {
        pivot = s_samp[r];
        BLK_COUNT(pivot);
        count = s_count;
        if (count >= DK && count <= CAP) ok = true;
        else if (count < DK) r = (2 * r + 8 > 31) ? 31 : (2 * r + 8);
        else r >>= 1;
    }
    if (!ok) {
        unsigned lo = 0, hi = 0xFFFFFFFFu;
        for (int it = 0; it < 34 && !ok; ++it) {
            unsigned mid = lo + ((hi - lo) >> 1);
            BLK_COUNT(mid);
            count = s_count;
            if (count >= DK && count <= CAP) { pivot = mid; ok = true; }
            else if (count < DK) hi = mid;      // pivot too high
            else lo = mid + 1;                  // pivot too low (count > CAP)
        }
        if (!ok) pivot = lo;                    // unreachable for distinct keys
    }

    // compact survivors from registers — ballot-aggregated (leader-lane atomic only)
    #pragma unroll
    for (int it = 0; it < 16; ++it) {
        bool pred = (key[it] >= pivot);
        unsigned m = __ballot_sync(0xFFFFFFFFu, pred);
        int base = 0;
        if (lane == 0 && m) base = atomicAdd(&s_cnt, __popc(m));
        base = __shfl_sync(0xFFFFFFFFu, base, 0);
        if (pred) {
            int pos = base + __popc(m & ((1u << lane) - 1u));
            if (pos < CAP) {
                int j = it * 256 + tid;
                s_buf[pos] = ((unsigned long long)key[it] << 32) | (unsigned)(~(unsigned)j);
            }
        }
    }
    __syncthreads();
    const int cnt = (s_cnt > CAP) ? CAP : s_cnt;

    // rank-by-count: exact descending rank (value desc, idx asc via ~idx)
    for (int t = tid; t < cnt; t += 256) {
        unsigned long long mine = s_buf[t];
        int rank = 0;
        int j = 0;
        for (; j + 3 < cnt; j += 4) {
            rank += (int)(s_buf[j]     > mine);
            rank += (int)(s_buf[j + 1] > mine);
            rank += (int)(s_buf[j + 2] > mine);
            rank += (int)(s_buf[j + 3] > mine);
        }
        for (; j < cnt; ++j) rank += (int)(s_buf[j] > mine);
        if (rank < DK) {
            unsigned u = (unsigned)(mine >> 32);
            int jj = (int)(~(unsigned)(mine & 0xFFFFFFFFu));
            s_met[rank] = -o2f(u);              // metric = -vals
            g_idxfull[(size_t)p * DK + rank] = jj;
        }
    }
    __syncthreads();

    // m_pre[o] = sum_c W_op1[o][c] * metric[c]  (ascending-c fma chain; exact ref order)
    if (tid < 64) {
        const float* w = W_op1 + tid * DK;
        float acc = __fmul_rn(__ldg(&w[0]), s_met[0]);
        #pragma unroll 4
        for (int c = 1; c < DK; ++c) acc = __fmaf_rn(__ldg(&w[c]), s_met[c], acc);
        g_mpre[(size_t)p * 64 + tid] = acc;
    }
}

// ---------------- K2: BN1 stats over (B,N) per channel (f64 accumulation; small) ----------------
__global__ __launch_bounds__(256) void stats1_kernel() {
    __shared__ double rs[256], rq[256];
    const int tid = threadIdx.x;
    double s = 0.0, q = 0.0;
    const int total = NPTS * 64;
    for (int e = blockIdx.x * 256 + tid; e < total; e += gridDim.x * 256) {
        double v = (double)g_mpre[e]; s += v; q += v * v;
    }
    rs[tid] = s; rq[tid] = q;
    __syncthreads();
    if (tid < 64) {
        double ss = rs[tid] + rs[tid + 64] + rs[tid + 128] + rs[tid + 192];
        double qq = rq[tid] + rq[tid + 64] + rq[tid + 128] + rq[tid + 192];
        atomicAdd(&g_sum1[tid], ss);
        atomicAdd(&g_sq1[tid], qq);
    }
}

// ---------------- K3: per-point dilation value + neighbor selection (BN1 finalized in-block) ----------------
__global__ __launch_bounds__(128) void select_kernel(const float* __restrict__ W_op11,
                                                     const float* __restrict__ b_op11,
                                                     const float* __restrict__ g_op1,
                                                     const float* __restrict__ b_op1) {
    __shared__ float sm[64], sr[64], sg[64], sb[64], sw[64];
    int t0 = threadIdx.x;
    if (t0 < 64) {
        const double n = (double)NPTS;
        double mean = g_sum1[t0] / n;
        double var  = g_sq1[t0] / n - mean * mean;
        sm[t0] = (float)mean;
        sr[t0] = __frsqrt_rn(__fadd_rn((float)var, EPSf));
        sg[t0] = g_op1[t0];   sb[t0] = b_op1[t0];
        sw[t0] = W_op11[t0];
    }
    __syncthreads();

    int pnt = blockIdx.x * blockDim.x + threadIdx.x;   // 256 blocks x 128 threads
    if (pnt >= NPTS) return;
    const float4* mp = (const float4*)(g_mpre + (size_t)pnt * 64);
    float acc = 0.0f;
    bool first = true;
    #pragma unroll
    for (int o4 = 0; o4 < 16; ++o4) {
        float4 v = mp[o4];
        int o = o4 * 4;
        float y0 = lrelu_exact(bn_apply(v.x, sm[o + 0], sr[o + 0], sg[o + 0], sb[o + 0]));
        float y1 = lrelu_exact(bn_apply(v.y, sm[o + 1], sr[o + 1], sg[o + 1], sb[o + 1]));
        float y2 = lrelu_exact(bn_apply(v.z, sm[o + 2], sr[o + 2], sg[o + 2], sb[o + 2]));
        float y3 = lrelu_exact(bn_apply(v.w, sm[o + 3], sr[o + 3], sg[o + 3], sb[o + 3]));
        if (first) { acc = __fmul_rn(sw[o], y0); first = false; }
        else       { acc = __fmaf_rn(sw[o], y0, acc); }
        acc = __fmaf_rn(sw[o + 1], y1, acc);
        acc = __fmaf_rn(sw[o + 2], y2, acc);
        acc = __fmaf_rn(sw[o + 3], y3, acc);
    }
    acc = __fadd_rn(acc, b_op11[0]);

    float m2 = 5.0f / (1.0f + expf(acc)) + 0.5f;   // 5*sigmoid(-m)+0.5
    float val = 0.f;
    if (m2 >= 0.5f && m2 < 1.5f) val += 1.f;
    if (m2 >= 1.5f && m2 < 2.5f) val += 2.f;
    if (m2 >= 2.5f && m2 < 3.5f) val += 3.f;
    if (m2 >= 3.5f && m2 < 4.5f) val += 4.f;
    if (m2 >= 4.5f && m2 <= 5.5f) val += 5.f;
    const int* row = g_idxfull + (size_t)pnt * DK;
    #pragma unroll
    for (int k = 0; k < Kn; ++k) {
        int sel = (int)((float)k * val);
        g_idxsel[(size_t)pnt * Kn + k] = row[sel];
    }
}

// ---------------- K4: h_pre stats (f32) + per-(point,o) max/min of h_pre ----------------
__global__ __launch_bounds__(256) void hstat_kernel(const float* __restrict__ x,
                                                    const float* __restrict__ W1) {
    __shared__ float  sfeat[64 * Kn * 6];   // 30720 B
    __shared__ float  sw[64 * 6];
    __shared__ float  sctr[64 * 3];
    __shared__ float  redS[256], redQ[256];

    const int tid = threadIdx.x;
    const int blk = blockIdx.x;            // 512 blocks, 64 points each
    const int b   = blk >> 6;
    const int n0  = (blk & 63) * 64;
    const float* xb = x + (size_t)b * 3 * Ndim;

    for (int t = tid; t < 64 * 6; t += 256) sw[t] = W1[t];
    if (tid < 192) { int c = tid / 64, pp = tid % 64; sctr[pp * 3 + c] = xb[c * Ndim + n0 + pp]; }
    __syncthreads();

    for (int t = tid; t < 64 * Kn; t += 256) {
        int pp = t / Kn, k = t % Kn;
        int j = g_idxsel[((size_t)(b * Ndim + n0 + pp)) * Kn + k];
        float c0 = sctr[pp * 3 + 0], c1 = sctr[pp * 3 + 1], c2 = sctr[pp * 3 + 2];
        float n0v = xb[j], n1v = xb[Ndim + j], n2v = xb[2 * Ndim + j];
        float* f = sfeat + t * 6;
        f[0] = __fsub_rn(n0v, c0); f[1] = __fsub_rn(n1v, c1); f[2] = __fsub_rn(n2v, c2);
        f[3] = c0;                 f[4] = c1;                 f[5] = c2;
    }
    __syncthreads();

    const int o = tid & 63, g = tid >> 6;
    float w0 = sw[o*6+0], w1 = sw[o*6+1], w2 = sw[o*6+2], w3 = sw[o*6+3], w4 = sw[o*6+4], w5 = sw[o*6+5];
    float s = 0.f, q = 0.f;
    for (int pp = g * 16; pp < g * 16 + 16; ++pp) {
        float hmax = -INFINITY, hmin = INFINITY;
        #pragma unroll
        for (int k = 0; k < Kn; ++k) {
            const float* f = sfeat + (pp * Kn + k) * 6;
            float hh = __fmul_rn(w0, f[0]);
            hh = __fmaf_rn(w1, f[1], hh);
            hh = __fmaf_rn(w2, f[2], hh);
            hh = __fmaf_rn(w3, f[3], hh);
            hh = __fmaf_rn(w4, f[4], hh);
            hh = __fmaf_rn(w5, f[5], hh);
            s += hh;
            q = __fmaf_rn(hh, hh, q);
            hmax = fmaxf(hmax, hh);
            hmin = fminf(hmin, hh);
        }
        size_t base = ((size_t)(b * Ndim + n0 + pp)) * 64 + o;
        g_hmax[base] = hmax;
        g_hmin[base] = hmin;
    }
    redS[tid] = s; redQ[tid] = q;
    __syncthreads();
    if (tid < 64) {
        float ss = redS[tid] + redS[tid + 64] + redS[tid + 128] + redS[tid + 192];
        float qq = redQ[tid] + redQ[tid + 64] + redQ[tid + 128] + redQ[tid + 192];
        atomicAdd(&g_sum2f[tid], ss);
        atomicAdd(&g_sq2f[tid], qq);
    }
}

// ---------------- K5: finalize h from hmax/hmin (monotone BN), BN2 finalized in-block ----------------
__global__ __launch_bounds__(256) void hfin2_kernel(const float* __restrict__ g1,
                                                    const float* __restrict__ b1,
                                                    float* __restrict__ out) {
    __shared__ float sh[64 * 64];          // 16 KB  [o][pp]
    __shared__ float redS[256];
    __shared__ float sm2[64], sr2[64];

    const int tid = threadIdx.x;
    const int blk = blockIdx.x;            // 512 blocks, 64 points each
    const int b   = blk >> 6;
    const int n0  = (blk & 63) * 64;

    if (tid < 64) {
        const double n = (double)NPTS * (double)Kn;
        double mean = (double)g_sum2f[tid] / n;
        double var  = (double)g_sq2f[tid] / n - mean * mean;
        sm2[tid] = (float)mean;
        sr2[tid] = __frsqrt_rn(__fadd_rn((float)var, EPSf));
    }
    __syncthreads();

    const int o = tid & 63, g = tid >> 6;
    const float mn = sm2[o], rs = sr2[o], ga = g1[o], be = b1[o];
    const bool usemax = (__fmul_rn(ga, rs) >= 0.0f);
    float lsum = 0.f;
    for (int pp = g; pp < 64; pp += 4) {
        size_t base = ((size_t)(b * Ndim + n0 + pp)) * 64 + o;
        float hv = usemax ? g_hmax[base] : g_hmin[base];
        float y = lrelu_exact(bn_apply(hv, mn, rs, ga, be));
        sh[o * 64 + pp] = y;
        lsum += y;
    }
    redS[tid] = lsum;
    __syncthreads();
    if (tid < 64) {
        float ss = redS[tid] + redS[tid + 64] + redS[tid + 128] + redS[tid + 192];
        atomicAdd(&g_ssumf[b * 64 + tid], ss);
    }
    // coalesced write: out[b][o][n]
    for (int t = tid; t < 64 * 64; t += 256) {
        int oo = t >> 6, pp = t & 63;
        out[((size_t)(b * 64 + oo)) * Ndim + n0 + pp] = sh[oo * 64 + pp];
    }
}

// ---------------- K6: SE block (tiny) ----------------
__global__ void se_kernel(const float* __restrict__ W_sq, const float* __restrict__ g_sq,
                          const float* __restrict__ b_sq, const float* __restrict__ W_ex,
                          const float* __restrict__ g_ex, const float* __restrict__ b_ex) {
    __shared__ float s1s[Bdim * 64];
    __shared__ float szr[Bdim * 8];
    const int tid = threadIdx.x;   // 64 threads
    for (int b = 0; b < Bdim; ++b)
        s1s[b * 64 + tid] = g_ssumf[b * 64 + tid] * (1.0f / (float)Ndim);
    __syncthreads();
    if (tid < 8) {
        const int j = tid;
        float z[Bdim];
        for (int b = 0; b < Bdim; ++b) {
            float a = __fmul_rn(W_sq[j * 64 + 0], s1s[b * 64 + 0]);
            for (int o = 1; o < 64; ++o) a = __fmaf_rn(W_sq[j * 64 + o], s1s[b * 64 + o], a);
            z[b] = a;
        }
        double mean = 0.0;
        for (int b = 0; b < Bdim; ++b) mean += (double)z[b];
        mean *= (1.0 / Bdim);
        double var = 0.0;
        for (int b = 0; b < Bdim; ++b) { double d = (double)z[b] - mean; var += d * d; }
        var *= (1.0 / Bdim);
        float mf = (float)mean;
        float rstd = __frsqrt_rn(__fadd_rn((float)var, EPSf));
        for (int b = 0; b < Bdim; ++b) {
            float t = bn_apply(z[b], mf, rstd, g_sq[j], b_sq[j]);
            szr[b * 8 + j] = t > 0.f ? t : 0.f;
        }
    }
    __syncthreads();
    {
        const int o = tid;
        float e[Bdim];
        for (int b = 0; b < Bdim; ++b) {
            float a = __fmul_rn(W_ex[o * 8 + 0], szr[b * 8 + 0]);
            #pragma unroll
            for (int j = 1; j < 8; ++j) a = __fmaf_rn(W_ex[o * 8 + j], szr[b * 8 + j], a);
            e[b] = a;
        }
        double mean = 0.0;
        for (int b = 0; b < Bdim; ++b) mean += (double)e[b];
        mean *= (1.0 / Bdim);
        double var = 0.0;
        for (int b = 0; b < Bdim; ++b) { double d = (double)e[b] - mean; var += d * d; }
        var *= (1.0 / Bdim);
        float mf = (float)mean;
        float rstd = __frsqrt_rn(__fadd_rn((float)var, EPSf));
        for (int b = 0; b < Bdim; ++b) {
            float t = bn_apply(e[b], mf, rstd, g_ex[o], b_ex[o]);
            g_gate[b * 64 + o] = 1.0f / (1.0f + expf(-t));
        }
    }
}

// ---------------- K7: apply gate ----------------
__global__ void scale_kernel(float* __restrict__ out) {
    const int total = NPTS * 64;
    for (int e = blockIdx.x * blockDim.x + threadIdx.x; e < total; e += gridDim.x * blockDim.x) {
        int bo = e >> 12;                  // (b*64+o) since layout [b][o][n], n=4096
        out[e] = __fmul_rn(out[e], g_gate[bo]);
    }
}

// ---------------- launch ----------------
extern "C" void kernel_launch(void* const* d_in, const int* in_sizes, int n_in,
                              void* d_out, int out_size) {
    const float* x      = (const float*)d_in[0];
    const float* W_op1  = (const float*)d_in[1];
    const float* g_op1  = (const float*)d_in[2];
    const float* b_op1  = (const float*)d_in[3];
    const float* W_op11 = (const float*)d_in[4];
    const float* b_op11 = (const float*)d_in[5];
    const float* W1     = (const float*)d_in[6];
    const float* g1     = (const float*)d_in[7];
    const float* b1     = (const float*)d_in[8];
    const float* W_sq   = (const float*)d_in[9];
    const float* g_sq   = (const float*)d_in[10];
    const float* b_sq   = (const float*)d_in[11];
    const float* W_ex   = (const float*)d_in[12];
    const float* g_ex   = (const float*)d_in[13];
    const float* b_ex   = (const float*)d_in[14];
    float* out = (float*)d_out;

    pre_kernel<<<64, 512>>>(x);
    dummy_kernel<<<1, 32>>>(1);            // align ncu capture window (#4) onto topk
    dummy_kernel<<<1, 32>>>(2);
    topk_kernel<<<NPTS, 256>>>(x, W_op1);  // <- launch #4: profiled
    stats1_kernel<<<64, 256>>>();
    select_kernel<<<NPTS / 128, 128>>>(W_op11, b_op11, g_op1, b_op1);
    hstat_kernel<<<512, 256>>>(x, W1);
    hfin2_kernel<<<512, 256>>>(g1, b1, out);
    se_kernel<<<1, 64>>>(W_sq, g_sq, b_sq, W_ex, g_ex, b_ex);
    scale_kernel<<<512, 256>>>(out);
}

// round 15
// speedup vs baseline: 1.6032x; 1.6032x over previous
#include <cuda_runtime.h>
#include <math.h>

#define Bdim   8
#define Cdim   3
#define Ndim   4096
#define DK     100
#define Kn     20
#define EPSf   1e-5f
#define SLOPEf 0.2f
#define NPTS   (Bdim * Ndim)   // 32768
#define CAP    512             // candidate buffer size

// ---------------- scratch (static device globals; no allocs) ----------------
__device__ float  g_xx[NPTS];             // per-point sum of squares (exact ref formula)
__device__ float  g_mpre[NPTS * 64];      // [b][n][o]  (o contiguous)
__device__ int    g_idxfull[NPTS * DK];   // top-100 neighbor indices per point
__device__ int    g_idxsel[NPTS * Kn];    // dilated 20 neighbor indices
__device__ float  g_hmax[NPTS * 64];      // per (point,o) max_k of h_pre
__device__ float  g_hmin[NPTS * 64];      // per (point,o) min_k of h_pre
__device__ double g_sum1[64], g_sq1[64];
__device__ float  g_sum2f[64], g_sq2f[64];
__device__ float  g_ssumf[Bdim * 64];     // per (b,o) sum of h over n
__device__ float  g_gate[Bdim * 64];      // SE gate s[b][o]
__device__ float  g_dummy[32];            // sink for profiler-alignment dummies

// ---------------- helpers ----------------
__device__ __forceinline__ unsigned f2o(float f) {
    unsigned u = __float_as_uint(f);
    return u ^ ((u & 0x80000000u) ? 0xFFFFFFFFu : 0x80000000u);
}
__device__ __forceinline__ float o2f(unsigned u) {
    unsigned v = u ^ ((u & 0x80000000u) ? 0x80000000u : 0xFFFFFFFFu);
    return __uint_as_float(v);
}
__device__ __forceinline__ float lrelu_exact(float v) {
    return v >= 0.0f ? v : __fmul_rn(SLOPEf, v);
}
// faithful BN apply: ((x - mean) * rstd) * gamma + beta, each op rounded separately
__device__ __forceinline__ float bn_apply(float x, float mean, float rstd, float gamma, float beta) {
    float xn = __fmul_rn(__fsub_rn(x, mean), rstd);
    return __fadd_rn(__fmul_rn(xn, gamma), beta);
}
// one pairwise key, exact reference op order
__device__ __forceinline__ unsigned pw_key(float xi0, float xi1, float xi2, float xxi,
                                           float a0, float a1, float a2, float xxj) {
    float inn = __fmul_rn(xi0, a0);
    inn = __fmaf_rn(xi1, a1, inn);
    inn = __fmaf_rn(xi2, a2, inn);
    float pw = __fsub_rn(__fsub_rn(__fmul_rn(2.0f, inn), xxi), xxj);
    return f2o(pw);
}
// warp-level bitonic sort of one value per lane; desc=true -> lane0 largest
__device__ __forceinline__ unsigned warp_sort32(unsigned v, unsigned lane, bool desc) {
    #pragma unroll
    for (unsigned k = 2; k <= 32; k <<= 1) {
        #pragma unroll
        for (unsigned j = k >> 1; j > 0; j >>= 1) {
            unsigned o = __shfl_xor_sync(0xFFFFFFFFu, v, j);
            bool blockdesc = ((lane & k) == 0) == desc;
            bool keepmax = (blockdesc == ((lane & j) == 0));
            unsigned mx = v > o ? v : o, mn = v > o ? o : v;
            v = keepmax ? mx : mn;
        }
    }
    return v;
}

// ---------------- K0: precompute xx (exact ref op order) + zero accumulators ----------------
__global__ __launch_bounds__(512) void pre_kernel(const float* __restrict__ x) {
    int t = blockIdx.x * blockDim.x + threadIdx.x;   // 64 x 512 = 32768
    if (blockIdx.x == 0) {
        if (threadIdx.x < 64) {
            g_sum1[threadIdx.x] = 0.0; g_sq1[threadIdx.x] = 0.0;
            g_sum2f[threadIdx.x] = 0.f; g_sq2f[threadIdx.x] = 0.f;
        }
        if (threadIdx.x < Bdim * 64) g_ssumf[threadIdx.x] = 0.f;
    }
    int b = t >> 12, j = t & (Ndim - 1);
    const float* xb = x + (size_t)b * 3 * Ndim;
    float a0 = xb[j], a1 = xb[Ndim + j], a2 = xb[2 * Ndim + j];
    g_xx[t] = __fadd_rn(__fadd_rn(__fmul_rn(a0, a0), __fmul_rn(a1, a1)),
                        __fmul_rn(a2, a2));
}

// ---------------- dummy: profiler-window alignment (deterministic, trivial) ----------------
__global__ void dummy_kernel(int tag) {
    if (threadIdx.x < 32) g_dummy[threadIdx.x] = (float)tag;
}

// ---------------- K1: per-row exact top-100: warp-sample pivot + rank-by-count ----------------
__global__ __launch_bounds__(256) void topk_kernel(const float* __restrict__ x,
                                                   const float* __restrict__ W_op1) {
    __shared__ unsigned           s_samp[256];     // 1 KB
    __shared__ unsigned long long s_buf[CAP];      // 4 KB
    __shared__ float              s_met[DK];
    __shared__ int                s_cnt;
    __shared__ int                s_count;
    __shared__ int                s_wcnt[8];

    const int p   = blockIdx.x;
    const int b   = p >> 12;
    const int tid = threadIdx.x;
    const unsigned lane = tid & 31, wid = tid >> 5;
    const float* xb = x + (size_t)b * 3 * Ndim;
    const float* gx = g_xx + ((size_t)b << 12);

    const int ii = p & (Ndim - 1);
    const float xi0 = xb[ii], xi1 = xb[Ndim + ii], xi2 = xb[2 * Ndim + ii];
    const float xxi = gx[ii];

    // distances -> 16 register keys per thread via float4 loads
    // j = it*1024 + 4*tid + l  (l = 0..3), coalesced 128-bit loads
    unsigned key[16];
    #pragma unroll
    for (int it = 0; it < 4; ++it) {
        int j0 = it * 1024 + 4 * tid;
        float4 ax = *(const float4*)(xb + j0);
        float4 bx = *(const float4*)(xb + Ndim + j0);
        float4 cx = *(const float4*)(xb + 2 * Ndim + j0);
        float4 xv = *(const float4*)(gx + j0);
        key[it * 4 + 0] = pw_key(xi0, xi1, xi2, xxi, ax.x, bx.x, cx.x, xv.x);
        key[it * 4 + 1] = pw_key(xi0, xi1, xi2, xxi, ax.y, bx.y, cx.y, xv.y);
        key[it * 4 + 2] = pw_key(xi0, xi1, xi2, xxi, ax.z, bx.z, cx.z, xv.z);
        key[it * 4 + 3] = pw_key(xi0, xi1, xi2, xxi, ax.w, bx.w, cx.w, xv.w);
    }
    if (tid == 0) s_cnt = 0;

    // each warp shuffle-sorts its 32 samples (key[0]) descending; no barriers
    s_samp[wid * 32 + lane] = warp_sort32(key[0], lane, true);
    __syncthreads();

    // warp 0 merges the 8 per-warp top-8s (64 values) -> sorted top-32 into s_samp[0..31]
    if (wid == 0) {
        unsigned v0 = s_samp[(lane >> 3) * 32 + (lane & 7)];         // warps 0-3 top8
        unsigned v1 = s_samp[((lane >> 3) + 4) * 32 + (lane & 7)];   // warps 4-7 top8
        v0 = warp_sort32(v0, lane, true);    // descending
        v1 = warp_sort32(v1, lane, false);   // ascending
        unsigned mx = v0 > v1 ? v0 : v1;     // top-32 of 64, bitonic
        #pragma unroll
        for (unsigned j = 16; j > 0; j >>= 1) {
            unsigned o = __shfl_xor_sync(0xFFFFFFFFu, mx, j);
            bool keepmax = ((lane & j) == 0);
            unsigned a = mx > o ? mx : o, c = mx > o ? o : mx;
            mx = keepmax ? a : c;
        }
        s_samp[lane] = mx;
    }
    __syncthreads();

    // collective count of keys >= piv (two-barrier version, R6)
    #define BLK_COUNT(piv)                                                    \
        {                                                                     \
            int c_ = 0;                                                       \
            _Pragma("unroll")                                                 \
            for (int it_ = 0; it_ < 16; ++it_) c_ += (key[it_] >= (piv));     \
            _Pragma("unroll")                                                 \
            for (int off_ = 16; off_ > 0; off_ >>= 1)                         \
                c_ += __shfl_xor_sync(0xFFFFFFFFu, c_, off_);                 \
            if (lane == 0) s_wcnt[wid] = c_;                                  \
            __syncthreads();                                                  \
            if (tid == 0) {                                                   \
                int t_ = 0;                                                   \
                _Pragma("unroll")                                             \
                for (int w_ = 0; w_ < 8; ++w_) t_ += s_wcnt[w_];              \
                s_count = t_;                                                 \
            }                                                                 \
            __syncthreads();                                                  \
        }

    // pivot search: sample-guided, then keyspace binary-search fallback
    unsigned pivot = 0;
    int count = 0;
    bool ok = false;
    int r = 8;
    for (int att = 0; att < 4 && !ok; ++att) {
        pivot = s_samp[r];
        BLK_COUNT(pivot);
        count = s_count;
        if (count >= DK && count <= CAP) ok = true;
        else if (count < DK) r = (2 * r + 8 > 31) ? 31 : (2 * r + 8);
        else r >>= 1;
    }
    if (!ok) {
        unsigned lo = 0, hi = 0xFFFFFFFFu;
        for (int it = 0; it < 34 && !ok; ++it) {
            unsigned mid = lo + ((hi - lo) >> 1);
            BLK_COUNT(mid);
            count = s_count;
            if (count >= DK && count <= CAP) { pivot = mid; ok = true; }
            else if (count < DK) hi = mid;      // pivot too high
            else lo = mid + 1;                  // pivot too low (count > CAP)
        }
        if (!ok) pivot = lo;                    // unreachable for distinct keys
    }

    // compact survivors from registers (predicated atomic: only ~140 threads hit it)
    #pragma unroll
    for (int it = 0; it < 16; ++it) {
        if (key[it] >= pivot) {
            int pos = atomicAdd(&s_cnt, 1);
            if (pos < CAP) {
                int j = (it >> 2) * 1024 + 4 * tid + (it & 3);
                s_buf[pos] = ((unsigned long long)key[it] << 32) | (unsigned)(~(unsigned)j);
            }
        }
    }
    __syncthreads();
    const int cnt = (s_cnt > CAP) ? CAP : s_cnt;

    // rank-by-count: exact descending rank (value desc, idx asc via ~idx)
    for (int t = tid; t < cnt; t += 256) {
        unsigned long long mine = s_buf[t];
        int rank = 0;
        int j = 0;
        for (; j + 3 < cnt; j += 4) {
            rank += (int)(s_buf[j]     > mine);
            rank += (int)(s_buf[j + 1] > mine);
            rank += (int)(s_buf[j + 2] > mine);
            rank += (int)(s_buf[j + 3] > mine);
        }
        for (; j < cnt; ++j) rank += (int)(s_buf[j] > mine);
        if (rank < DK) {
            unsigned u = (unsigned)(mine >> 32);
            int jj = (int)(~(unsigned)(mine & 0xFFFFFFFFu));
            s_met[rank] = -o2f(u);              // metric = -vals
            g_idxfull[(size_t)p * DK + rank] = jj;
        }
    }
    __syncthreads();

    // m_pre[o] = sum_c W_op1[o][c] * metric[c]  (ascending-c fma chain; exact ref order)
    if (tid < 64) {
        const float* w = W_op1 + tid * DK;
        float acc = __fmul_rn(__ldg(&w[0]), s_met[0]);
        #pragma unroll 4
        for (int c = 1; c < DK; ++c) acc = __fmaf_rn(__ldg(&w[c]), s_met[c], acc);
        g_mpre[(size_t)p * 64 + tid] = acc;
    }
}

// ---------------- K2: BN1 stats over (B,N) per channel (f64 accumulation; small) ----------------
__global__ __launch_bounds__(256) void stats1_kernel() {
    __shared__ double rs[256], rq[256];
    const int tid = threadIdx.x;
    double s = 0.0, q = 0.0;
    const int total = NPTS * 64;
    for (int e = blockIdx.x * 256 + tid; e < total; e += gridDim.x * 256) {
        double v = (double)g_mpre[e]; s += v; q += v * v;
    }
    rs[tid] = s; rq[tid] = q;
    __syncthreads();
    if (tid < 64) {
        double ss = rs[tid] + rs[tid + 64] + rs[tid + 128] + rs[tid + 192];
        double qq = rq[tid] + rq[tid + 64] + rq[tid + 128] + rq[tid + 192];
        atomicAdd(&g_sum1[tid], ss);
        atomicAdd(&g_sq1[tid], qq);
    }
}

// ---------------- K3: per-point dilation value + neighbor selection (BN1 finalized in-block) ----------------
__global__ __launch_bounds__(128) void select_kernel(const float* __restrict__ W_op11,
                                                     const float* __restrict__ b_op11,
                                                     const float* __restrict__ g_op1,
                                                     const float* __restrict__ b_op1) {
    __shared__ float sm[64], sr[64], sg[64], sb[64], sw[64];
    int t0 = threadIdx.x;
    if (t0 < 64) {
        const double n = (double)NPTS;
        double mean = g_sum1[t0] / n;
        double var  = g_sq1[t0] / n - mean * mean;
        sm[t0] = (float)mean;
        sr[t0] = __frsqrt_rn(__fadd_rn((float)var, EPSf));
        sg[t0] = g_op1[t0];   sb[t0] = b_op1[t0];
        sw[t0] = W_op11[t0];
    }
    __syncthreads();

    int pnt = blockIdx.x * blockDim.x + threadIdx.x;   // 256 blocks x 128 threads
    if (pnt >= NPTS) return;
    const float4* mp = (const float4*)(g_mpre + (size_t)pnt * 64);
    float acc = 0.0f;
    bool first = true;
    #pragma unroll
    for (int o4 = 0; o4 < 16; ++o4) {
        float4 v = mp[o4];
        int o = o4 * 4;
        float y0 = lrelu_exact(bn_apply(v.x, sm[o + 0], sr[o + 0], sg[o + 0], sb[o + 0]));
        float y1 = lrelu_exact(bn_apply(v.y, sm[o + 1], sr[o + 1], sg[o + 1], sb[o + 1]));
        float y2 = lrelu_exact(bn_apply(v.z, sm[o + 2], sr[o + 2], sg[o + 2], sb[o + 2]));
        float y3 = lrelu_exact(bn_apply(v.w, sm[o + 3], sr[o + 3], sg[o + 3], sb[o + 3]));
        if (first) { acc = __fmul_rn(sw[o], y0); first = false; }
        else       { acc = __fmaf_rn(sw[o], y0, acc); }
        acc = __fmaf_rn(sw[o + 1], y1, acc);
        acc = __fmaf_rn(sw[o + 2], y2, acc);
        acc = __fmaf_rn(sw[o + 3], y3, acc);
    }
    acc = __fadd_rn(acc, b_op11[0]);

    float m2 = 5.0f / (1.0f + expf(acc)) + 0.5f;   // 5*sigmoid(-m)+0.5
    float val = 0.f;
    if (m2 >= 0.5f && m2 < 1.5f) val += 1.f;
    if (m2 >= 1.5f && m2 < 2.5f) val += 2.f;
    if (m2 >= 2.5f && m2 < 3.5f) val += 3.f;
    if (m2 >= 3.5f && m2 < 4.5f) val += 4.f;
    if (m2 >= 4.5f && m2 <= 5.5f) val += 5.f;
    const int* row = g_idxfull + (size_t)pnt * DK;
    #pragma unroll
    for (int k = 0; k < Kn; ++k) {
        int sel = (int)((float)k * val);
        g_idxsel[(size_t)pnt * Kn + k] = row[sel];
    }
}

// ---------------- K4: h_pre stats (f32) + per-(point,o) max/min of h_pre ----------------
__global__ __launch_bounds__(256) void hstat_kernel(const float* __restrict__ x,
                                                    const float* __restrict__ W1) {
    __shared__ float  sfeat[64 * Kn * 6];   // 30720 B
    __shared__ float  sw[64 * 6];
    __shared__ float  sctr[64 * 3];
    __shared__ float  redS[256], redQ[256];

    const int tid = threadIdx.x;
    const int blk = blockIdx.x;            // 512 blocks, 64 points each
    const int b   = blk >> 6;
    const int n0  = (blk & 63) * 64;
    const float* xb = x + (size_t)b * 3 * Ndim;

    for (int t = tid; t < 64 * 6; t += 256) sw[t] = W1[t];
    if (tid < 192) { int c = tid / 64, pp = tid % 64; sctr[pp * 3 + c] = xb[c * Ndim + n0 + pp]; }
    __syncthreads();

    for (int t = tid; t < 64 * Kn; t += 256) {
        int pp = t / Kn, k = t % Kn;
        int j = g_idxsel[((size_t)(b * Ndim + n0 + pp)) * Kn + k];
        float c0 = sctr[pp * 3 + 0], c1 = sctr[pp * 3 + 1], c2 = sctr[pp * 3 + 2];
        float n0v = xb[j], n1v = xb[Ndim + j], n2v = xb[2 * Ndim + j];
        float* f = sfeat + t * 6;
        f[0] = __fsub_rn(n0v, c0); f[1] = __fsub_rn(n1v, c1); f[2] = __fsub_rn(n2v, c2);
        f[3] = c0;                 f[4] = c1;                 f[5] = c2;
    }
    __syncthreads();

    const int o = tid & 63, g = tid >> 6;
    float w0 = sw[o*6+0], w1 = sw[o*6+1], w2 = sw[o*6+2], w3 = sw[o*6+3], w4 = sw[o*6+4], w5 = sw[o*6+5];
    float s = 0.f, q = 0.f;
    for (int pp = g * 16; pp < g * 16 + 16; ++pp) {
        float hmax = -INFINITY, hmin = INFINITY;
        #pragma unroll
        for (int k = 0; k < Kn; ++k) {
            const float* f = sfeat + (pp * Kn + k) * 6;
            float hh = __fmul_rn(w0, f[0]);
            hh = __fmaf_rn(w1, f[1], hh);
            hh = __fmaf_rn(w2, f[2], hh);
            hh = __fmaf_rn(w3, f[3], hh);
            hh = __fmaf_rn(w4, f[4], hh);
            hh = __fmaf_rn(w5, f[5], hh);
            s += hh;
            q = __fmaf_rn(hh, hh, q);
            hmax = fmaxf(hmax, hh);
            hmin = fminf(hmin, hh);
        }
        size_t base = ((size_t)(b * Ndim + n0 + pp)) * 64 + o;
        g_hmax[base] = hmax;
        g_hmin[base] = hmin;
    }
    redS[tid] = s; redQ[tid] = q;
    __syncthreads();
    if (tid < 64) {
        float ss = redS[tid] + redS[tid + 64] + redS[tid + 128] + redS[tid + 192];
        float qq = redQ[tid] + redQ[tid + 64] + redQ[tid + 128] + redQ[tid + 192];
        atomicAdd(&g_sum2f[tid], ss);
        atomicAdd(&g_sq2f[tid], qq);
    }
}

// ---------------- K5: finalize h from hmax/hmin (monotone BN), BN2 finalized in-block ----------------
__global__ __launch_bounds__(256) void hfin2_kernel(const float* __restrict__ g1,
                                                    const float* __restrict__ b1,
                                                    float* __restrict__ out) {
    __shared__ float sh[64 * 64];          // 16 KB  [o][pp]
    __shared__ float redS[256];
    __shared__ float sm2[64], sr2[64];

    const int tid = threadIdx.x;
    const int blk = blockIdx.x;            // 512 blocks, 64 points each
    const int b   = blk >> 6;
    const int n0  = (blk & 63) * 64;

    if (tid < 64) {
        const double n = (double)NPTS * (double)Kn;
        double mean = (double)g_sum2f[tid] / n;
        double var  = (double)g_sq2f[tid] / n - mean * mean;
        sm2[tid] = (float)mean;
        sr2[tid] = __frsqrt_rn(__fadd_rn((float)var, EPSf));
    }
    __syncthreads();

    const int o = tid & 63, g = tid >> 6;
    const float mn = sm2[o], rs = sr2[o], ga = g1[o], be = b1[o];
    const bool usemax = (__fmul_rn(ga, rs) >= 0.0f);
    float lsum = 0.f;
    for (int pp = g; pp < 64; pp += 4) {
        size_t base = ((size_t)(b * Ndim + n0 + pp)) * 64 + o;
        float hv = usemax ? g_hmax[base] : g_hmin[base];
        float y = lrelu_exact(bn_apply(hv, mn, rs, ga, be));
        sh[o * 64 + pp] = y;
        lsum += y;
    }
    redS[tid] = lsum;
    __syncthreads();
    if (tid < 64) {
        float ss = redS[tid] + redS[tid + 64] + redS[tid + 128] + redS[tid + 192];
        atomicAdd(&g_ssumf[b * 64 + tid], ss);
    }
    // coalesced write: out[b][o][n]
    for (int t = tid; t < 64 * 64; t += 256) {
        int oo = t >> 6, pp = t & 63;
        out[((size_t)(b * 64 + oo)) * Ndim + n0 + pp] = sh[oo * 64 + pp];
    }
}

// ---------------- K6: SE block (tiny) ----------------
__global__ void se_kernel(const float* __restrict__ W_sq, const float* __restrict__ g_sq,
                          const float* __restrict__ b_sq, const float* __restrict__ W_ex,
                          const float* __restrict__ g_ex, const float* __restrict__ b_ex) {
    __shared__ float s1s[Bdim * 64];
    __shared__ float szr[Bdim * 8];
    const int tid = threadIdx.x;   // 64 threads
    for (int b = 0; b < Bdim; ++b)
        s1s[b * 64 + tid] = g_ssumf[b * 64 + tid] * (1.0f / (float)Ndim);
    __syncthreads();
    if (tid < 8) {
        const int j = tid;
        float z[Bdim];
        for (int b = 0; b < Bdim; ++b) {
            float a = __fmul_rn(W_sq[j * 64 + 0], s1s[b * 64 + 0]);
            for (int o = 1; o < 64; ++o) a = __fmaf_rn(W_sq[j * 64 + o], s1s[b * 64 + o], a);
            z[b] = a;
        }
        double mean = 0.0;
        for (int b = 0; b < Bdim; ++b) mean += (double)z[b];
        mean *= (1.0 / Bdim);
        double var = 0.0;
        for (int b = 0; b < Bdim; ++b) { double d = (double)z[b] - mean; var += d * d; }
        var *= (1.0 / Bdim);
        float mf = (float)mean;
        float rstd = __frsqrt_rn(__fadd_rn((float)var, EPSf));
        for (int b = 0; b < Bdim; ++b) {
            float t = bn_apply(z[b], mf, rstd, g_sq[j], b_sq[j]);
            szr[b * 8 + j] = t > 0.f ? t : 0.f;
        }
    }
    __syncthreads();
    {
        const int o = tid;
        float e[Bdim];
        for (int b = 0; b < Bdim; ++b) {
            float a = __fmul_rn(W_ex[o * 8 + 0], szr[b * 8 + 0]);
            #pragma unroll
            for (int j = 1; j < 8; ++j) a = __fmaf_rn(W_ex[o * 8 + j], szr[b * 8 + j], a);
            e[b] = a;
        }
        double mean = 0.0;
        for (int b = 0; b < Bdim; ++b) mean += (double)e[b];
        mean *= (1.0 / Bdim);
        double var = 0.0;
        for (int b = 0; b < Bdim; ++b) { double d = (double)e[b] - mean; var += d * d; }
        var *= (1.0 / Bdim);
        float mf = (float)mean;
        float rstd = __frsqrt_rn(__fadd_rn((float)var, EPSf));
        for (int b = 0; b < Bdim; ++b) {
            float t = bn_apply(e[b], mf, rstd, g_ex[o], b_ex[o]);
            g_gate[b * 64 + o] = 1.0f / (1.0f + expf(-t));
        }
    }
}

// ---------------- K7: apply gate ----------------
__global__ void scale_kernel(float* __restrict__ out) {
    const int total = NPTS * 64;
    for (int e = blockIdx.x * blockDim.x + threadIdx.x; e < total; e += gridDim.x * blockDim.x) {
        int bo = e >> 12;                  // (b*64+o) since layout [b][o][n], n=4096
        out[e] = __fmul_rn(out[e], g_gate[bo]);
    }
}

// ---------------- launch ----------------
extern "C" void kernel_launch(void* const* d_in, const int* in_sizes, int n_in,
                              void* d_out, int out_size) {
    const float* x      = (const float*)d_in[0];
    const float* W_op1  = (const float*)d_in[1];
    const float* g_op1  = (const float*)d_in[2];
    const float* b_op1  = (const float*)d_in[3];
    const float* W_op11 = (const float*)d_in[4];
    const float* b_op11 = (const float*)d_in[5];
    const float* W1     = (const float*)d_in[6];
    const float* g1     = (const float*)d_in[7];
    const float* b1     = (const float*)d_in[8];
    const float* W_sq   = (const float*)d_in[9];
    const float* g_sq   = (const float*)d_in[10];
    const float* b_sq   = (const float*)d_in[11];
    const float* W_ex   = (const float*)d_in[12];
    const float* g_ex   = (const float*)d_in[13];
    const float* b_ex   = (const float*)d_in[14];
    float* out = (float*)d_out;

    pre_kernel<<<64, 512>>>(x);
    dummy_kernel<<<1, 32>>>(1);            // keep topk at launch #4 (ncu window)
    dummy_kernel<<<1, 32>>>(2);
    topk_kernel<<<NPTS, 256>>>(x, W_op1);  // <- profiled
    stats1_kernel<<<64, 256>>>();
    select_kernel<<<NPTS / 128, 128>>>(W_op11, b_op11, g_op1, b_op1);
    hstat_kernel<<<512, 256>>>(x, W1);
    hfin2_kernel<<<512, 256>>>(g1, b1, out);
    se_kernel<<<1, 64>>>(W_sq, g_sq, b_sq, W_ex, g_ex, b_ex);
    scale_kernel<<<512, 256>>>(out);
}

// round 16
// speedup vs baseline: 1.9073x; 1.1897x over previous
#include <cuda_runtime.h>
#include <math.h>

#define Bdim   8
#define Cdim   3
#define Ndim   4096
#define DK     100
#define Kn     20
#define EPSf   1e-5f
#define SLOPEf 0.2f
#define NPTS   (Bdim * Ndim)   // 32768
#define CAP    256             // candidate buffer size (merge-rank is 256-wide)

// ---------------- scratch (static device globals; no allocs) ----------------
__device__ float  g_xx[NPTS];             // per-point sum of squares (exact ref formula)
__device__ float  g_mpre[NPTS * 64];      // [b][n][o]  (o contiguous)
__device__ int    g_idxfull[NPTS * DK];   // top-100 neighbor indices per point
__device__ int    g_idxsel[NPTS * Kn];    // dilated 20 neighbor indices
__device__ float  g_hmax[NPTS * 64];      // per (point,o) max_k of h_pre
__device__ float  g_hmin[NPTS * 64];      // per (point,o) min_k of h_pre
__device__ double g_sum1[64], g_sq1[64];
__device__ float  g_sum2f[64], g_sq2f[64];
__device__ float  g_ssumf[Bdim * 64];     // per (b,o) sum of h over n
__device__ float  g_gate[Bdim * 64];      // SE gate s[b][o]
__device__ float  g_dummy[32];            // sink for profiler-alignment dummies

// ---------------- helpers ----------------
__device__ __forceinline__ unsigned f2o(float f) {
    unsigned u = __float_as_uint(f);
    return u ^ ((u & 0x80000000u) ? 0xFFFFFFFFu : 0x80000000u);
}
__device__ __forceinline__ float o2f(unsigned u) {
    unsigned v = u ^ ((u & 0x80000000u) ? 0x80000000u : 0xFFFFFFFFu);
    return __uint_as_float(v);
}
__device__ __forceinline__ float lrelu_exact(float v) {
    return v >= 0.0f ? v : __fmul_rn(SLOPEf, v);
}
// faithful BN apply: ((x - mean) * rstd) * gamma + beta, each op rounded separately
__device__ __forceinline__ float bn_apply(float x, float mean, float rstd, float gamma, float beta) {
    float xn = __fmul_rn(__fsub_rn(x, mean), rstd);
    return __fadd_rn(__fmul_rn(xn, gamma), beta);
}
// warp-level bitonic sort of one 32-bit value per lane; desc=true -> lane0 largest
__device__ __forceinline__ unsigned warp_sort32(unsigned v, unsigned lane, bool desc) {
    #pragma unroll
    for (unsigned k = 2; k <= 32; k <<= 1) {
        #pragma unroll
        for (unsigned j = k >> 1; j > 0; j >>= 1) {
            unsigned o = __shfl_xor_sync(0xFFFFFFFFu, v, j);
            bool blockdesc = ((lane & k) == 0) == desc;
            bool keepmax = (blockdesc == ((lane & j) == 0));
            unsigned mx = v > o ? v : o, mn = v > o ? o : v;
            v = keepmax ? mx : mn;
        }
    }
    return v;
}
// warp-level bitonic sort of one u64 per lane, descending (lane0 largest)
__device__ __forceinline__ unsigned long long warp_sort32_u64(unsigned long long v, unsigned lane) {
    #pragma unroll
    for (unsigned k = 2; k <= 32; k <<= 1) {
        #pragma unroll
        for (unsigned j = k >> 1; j > 0; j >>= 1) {
            unsigned long long o = __shfl_xor_sync(0xFFFFFFFFu, v, j);
            bool blockdesc = ((lane & k) == 0);
            bool keepmax = (blockdesc == ((lane & j) == 0));
            unsigned long long mx = v > o ? v : o, mn = v > o ? o : v;
            v = keepmax ? mx : mn;
        }
    }
    return v;
}

// ---------------- K0: precompute xx (exact ref op order) + zero accumulators ----------------
__global__ __launch_bounds__(512) void pre_kernel(const float* __restrict__ x) {
    int t = blockIdx.x * blockDim.x + threadIdx.x;   // 64 x 512 = 32768
    if (blockIdx.x == 0) {
        if (threadIdx.x < 64) {
            g_sum1[threadIdx.x] = 0.0; g_sq1[threadIdx.x] = 0.0;
            g_sum2f[threadIdx.x] = 0.f; g_sq2f[threadIdx.x] = 0.f;
        }
        if (threadIdx.x < Bdim * 64) g_ssumf[threadIdx.x] = 0.f;
    }
    int b = t >> 12, j = t & (Ndim - 1);
    const float* xb = x + (size_t)b * 3 * Ndim;
    float a0 = xb[j], a1 = xb[Ndim + j], a2 = xb[2 * Ndim + j];
    g_xx[t] = __fadd_rn(__fadd_rn(__fmul_rn(a0, a0), __fmul_rn(a1, a1)),
                        __fmul_rn(a2, a2));
}

// ---------------- dummy: profiler-window alignment (deterministic, trivial) ----------------
__global__ void dummy_kernel(int tag) {
    if (threadIdx.x < 32) g_dummy[threadIdx.x] = (float)tag;
}

// ---------------- K1: per-row exact top-100: warp-sample pivot + warp-sort merge-rank ----------------
__global__ __launch_bounds__(256) void topk_kernel(const float* __restrict__ x,
                                                   const float* __restrict__ W_op1) {
    __shared__ unsigned           s_samp[256];     // 1 KB
    __shared__ unsigned long long s_buf[CAP];      // 2 KB
    __shared__ float              s_met[DK];
    __shared__ int                s_cnt;
    __shared__ int                s_count;
    __shared__ int                s_wcnt[8];

    const int p   = blockIdx.x;
    const int b   = p >> 12;
    const int tid = threadIdx.x;
    const unsigned lane = tid & 31, wid = tid >> 5;
    const float* xb = x + (size_t)b * 3 * Ndim;
    const float* gx = g_xx + ((size_t)b << 12);

    const int ii = p & (Ndim - 1);
    const float xi0 = xb[ii], xi1 = xb[Ndim + ii], xi2 = xb[2 * Ndim + ii];
    const float xxi = gx[ii];

    // distances -> 16 register keys per thread (j = it*256 + tid, coalesced, scalar loads)
    unsigned key[16];
    #pragma unroll
    for (int it = 0; it < 16; ++it) {
        int j = it * 256 + tid;
        float a0 = xb[j], a1 = xb[Ndim + j], a2 = xb[2 * Ndim + j];
        float inn = __fmul_rn(xi0, a0);
        inn = __fmaf_rn(xi1, a1, inn);
        inn = __fmaf_rn(xi2, a2, inn);
        float pw = __fsub_rn(__fsub_rn(__fmul_rn(2.0f, inn), xxi), gx[j]);
        key[it] = f2o(pw);
    }
    if (tid == 0) s_cnt = 0;

    // each warp shuffle-sorts its 32 samples (key[0]) descending; no barriers
    s_samp[wid * 32 + lane] = warp_sort32(key[0], lane, true);
    __syncthreads();

    // warp 0 merges the 8 per-warp top-8s (64 values) -> sorted top-32 into s_samp[0..31]
    if (wid == 0) {
        unsigned v0 = s_samp[(lane >> 3) * 32 + (lane & 7)];         // warps 0-3 top8
        unsigned v1 = s_samp[((lane >> 3) + 4) * 32 + (lane & 7)];   // warps 4-7 top8
        v0 = warp_sort32(v0, lane, true);    // descending
        v1 = warp_sort32(v1, lane, false);   // ascending
        unsigned mx = v0 > v1 ? v0 : v1;     // top-32 of 64, bitonic
        #pragma unroll
        for (unsigned j = 16; j > 0; j >>= 1) {
            unsigned o = __shfl_xor_sync(0xFFFFFFFFu, mx, j);
            bool keepmax = ((lane & j) == 0);
            unsigned a = mx > o ? mx : o, c = mx > o ? o : mx;
            mx = keepmax ? a : c;
        }
        s_samp[lane] = mx;
    }
    __syncthreads();

    // collective count of keys >= piv (two-barrier version, R6)
    #define BLK_COUNT(piv)                                                    \
        {                                                                     \
            int c_ = 0;                                                       \
            _Pragma("unroll")                                                 \
            for (int it_ = 0; it_ < 16; ++it_) c_ += (key[it_] >= (piv));     \
            _Pragma("unroll")                                                 \
            for (int off_ = 16; off_ > 0; off_ >>= 1)                         \
                c_ += __shfl_xor_sync(0xFFFFFFFFu, c_, off_);                 \
            if (lane == 0) s_wcnt[wid] = c_;                                  \
            __syncthreads();                                                  \
            if (tid == 0) {                                                   \
                int t_ = 0;                                                   \
                _Pragma("unroll")                                             \
                for (int w_ = 0; w_ < 8; ++w_) t_ += s_wcnt[w_];              \
                s_count = t_;                                                 \
            }                                                                 \
            __syncthreads();                                                  \
        }

    // pivot search: sample-guided, then keyspace binary-search fallback; accept [DK, CAP]
    unsigned pivot = 0;
    int count = 0;
    bool ok = false;
    int r = 8;
    for (int att = 0; att < 4 && !ok; ++att) {
        pivot = s_samp[r];
        BLK_COUNT(pivot);
        count = s_count;
        if (count >= DK && count <= CAP) ok = true;
        else if (count < DK) r = (2 * r + 8 > 31) ? 31 : (2 * r + 8);
        else r >>= 1;
    }
    if (!ok) {
        unsigned lo = 0, hi = 0xFFFFFFFFu;
        for (int it = 0; it < 34 && !ok; ++it) {
            unsigned mid = lo + ((hi - lo) >> 1);
            BLK_COUNT(mid);
            count = s_count;
            if (count >= DK && count <= CAP) { pivot = mid; ok = true; }
            else if (count < DK) hi = mid;      // pivot too high
            else lo = mid + 1;                  // pivot too low (count > CAP)
        }
        if (!ok) pivot = lo;                    // unreachable for distinct keys
    }

    // compact survivors from registers (predicated atomic; ~140 survivors total)
    #pragma unroll
    for (int it = 0; it < 16; ++it) {
        if (key[it] >= pivot) {
            int pos = atomicAdd(&s_cnt, 1);
            if (pos < CAP) {
                int j = it * 256 + tid;
                s_buf[pos] = ((unsigned long long)key[it] << 32) | (unsigned)(~(unsigned)j);
            }
        }
    }
    __syncthreads();
    const int cnt = (s_cnt > CAP) ? CAP : s_cnt;   // exact count, ≤ CAP by pivot guarantee
    // pad to CAP with 0 (0 < any real packed key; equal zeros rank >= cnt >= DK -> skipped)
    for (int z = cnt + tid; z < CAP; z += 256) s_buf[z] = 0ull;
    __syncthreads();

    // per-warp sort of its own 32-slot segment (descending), registers only
    unsigned long long mine = warp_sort32_u64(s_buf[tid], lane);
    s_buf[tid] = mine;     // each warp touches only its own segment
    __syncthreads();

    // merge-rank: rank = in-segment position + count-greater in the other 7 sorted segments
    {
        int rank = (int)lane;
        #pragma unroll
        for (int s2 = 0; s2 < 8; ++s2) {
            if (s2 == (int)wid) continue;
            const unsigned long long* seg = s_buf + s2 * 32;
            if (seg[31] > mine) { rank += 32; continue; }
            int pos = 0;
            #pragma unroll
            for (int st = 16; st > 0; st >>= 1)
                if (seg[pos + st - 1] > mine) pos += st;
            rank += pos;
        }
        if (rank < DK) {
            unsigned u = (unsigned)(mine >> 32);
            int jj = (int)(~(unsigned)(mine & 0xFFFFFFFFu));
            s_met[rank] = -o2f(u);              // metric = -vals
            g_idxfull[(size_t)p * DK + rank] = jj;
        }
    }
    __syncthreads();

    // m_pre[o] = sum_c W_op1[o][c] * metric[c]  (ascending-c fma chain; exact ref order)
    if (tid < 64) {
        const float* w = W_op1 + tid * DK;
        float acc = __fmul_rn(__ldg(&w[0]), s_met[0]);
        #pragma unroll 4
        for (int c = 1; c < DK; ++c) acc = __fmaf_rn(__ldg(&w[c]), s_met[c], acc);
        g_mpre[(size_t)p * 64 + tid] = acc;
    }
}

// ---------------- K2: BN1 stats over (B,N) per channel (f64 accumulation; small) ----------------
__global__ __launch_bounds__(256) void stats1_kernel() {
    __shared__ double rs[256], rq[256];
    const int tid = threadIdx.x;
    double s = 0.0, q = 0.0;
    const int total = NPTS * 64;
    for (int e = blockIdx.x * 256 + tid; e < total; e += gridDim.x * 256) {
        double v = (double)g_mpre[e]; s += v; q += v * v;
    }
    rs[tid] = s; rq[tid] = q;
    __syncthreads();
    if (tid < 64) {
        double ss = rs[tid] + rs[tid + 64] + rs[tid + 128] + rs[tid + 192];
        double qq = rq[tid] + rq[tid + 64] + rq[tid + 128] + rq[tid + 192];
        atomicAdd(&g_sum1[tid], ss);
        atomicAdd(&g_sq1[tid], qq);
    }
}

// ---------------- K3: per-point dilation value + neighbor selection (BN1 finalized in-block) ----------------
__global__ __launch_bounds__(128) void select_kernel(const float* __restrict__ W_op11,
                                                     const float* __restrict__ b_op11,
                                                     const float* __restrict__ g_op1,
                                                     const float* __restrict__ b_op1) {
    __shared__ float sm[64], sr[64], sg[64], sb[64], sw[64];
    int t0 = threadIdx.x;
    if (t0 < 64) {
        const double n = (double)NPTS;
        double mean = g_sum1[t0] / n;
        double var  = g_sq1[t0] / n - mean * mean;
        sm[t0] = (float)mean;
        sr[t0] = __frsqrt_rn(__fadd_rn((float)var, EPSf));
        sg[t0] = g_op1[t0];   sb[t0] = b_op1[t0];
        sw[t0] = W_op11[t0];
    }
    __syncthreads();

    int pnt = blockIdx.x * blockDim.x + threadIdx.x;   // 256 blocks x 128 threads
    if (pnt >= NPTS) return;
    const float4* mp = (const float4*)(g_mpre + (size_t)pnt * 64);
    float acc = 0.0f;
    bool first = true;
    #pragma unroll
    for (int o4 = 0; o4 < 16; ++o4) {
        float4 v = mp[o4];
        int o = o4 * 4;
        float y0 = lrelu_exact(bn_apply(v.x, sm[o + 0], sr[o + 0], sg[o + 0], sb[o + 0]));
        float y1 = lrelu_exact(bn_apply(v.y, sm[o + 1], sr[o + 1], sg[o + 1], sb[o + 1]));
        float y2 = lrelu_exact(bn_apply(v.z, sm[o + 2], sr[o + 2], sg[o + 2], sb[o + 2]));
        float y3 = lrelu_exact(bn_apply(v.w, sm[o + 3], sr[o + 3], sg[o + 3], sb[o + 3]));
        if (first) { acc = __fmul_rn(sw[o], y0); first = false; }
        else       { acc = __fmaf_rn(sw[o], y0, acc); }
        acc = __fmaf_rn(sw[o + 1], y1, acc);
        acc = __fmaf_rn(sw[o + 2], y2, acc);
        acc = __fmaf_rn(sw[o + 3], y3, acc);
    }
    acc = __fadd_rn(acc, b_op11[0]);

    float m2 = 5.0f / (1.0f + expf(acc)) + 0.5f;   // 5*sigmoid(-m)+0.5
    float val = 0.f;
    if (m2 >= 0.5f && m2 < 1.5f) val += 1.f;
    if (m2 >= 1.5f && m2 < 2.5f) val += 2.f;
    if (m2 >= 2.5f && m2 < 3.5f) val += 3.f;
    if (m2 >= 3.5f && m2 < 4.5f) val += 4.f;
    if (m2 >= 4.5f && m2 <= 5.5f) val += 5.f;
    const int* row = g_idxfull + (size_t)pnt * DK;
    #pragma unroll
    for (int k = 0; k < Kn; ++k) {
        int sel = (int)((float)k * val);
        g_idxsel[(size_t)pnt * Kn + k] = row[sel];
    }
}

// ---------------- K4: h_pre stats (f32) + per-(point,o) max/min of h_pre ----------------
__global__ __launch_bounds__(256) void hstat_kernel(const float* __restrict__ x,
                                                    const float* __restrict__ W1) {
    __shared__ float  sfeat[64 * Kn * 6];   // 30720 B
    __shared__ float  sw[64 * 6];
    __shared__ float  sctr[64 * 3];
    __shared__ float  redS[256], redQ[256];

    const int tid = threadIdx.x;
    const int blk = blockIdx.x;            // 512 blocks, 64 points each
    const int b   = blk >> 6;
    const int n0  = (blk & 63) * 64;
    const float* xb = x + (size_t)b * 3 * Ndim;

    for (int t = tid; t < 64 * 6; t += 256) sw[t] = W1[t];
    if (tid < 192) { int c = tid / 64, pp = tid % 64; sctr[pp * 3 + c] = xb[c * Ndim + n0 + pp]; }
    __syncthreads();

    for (int t = tid; t < 64 * Kn; t += 256) {
        int pp = t / Kn, k = t % Kn;
        int j = g_idxsel[((size_t)(b * Ndim + n0 + pp)) * Kn + k];
        float c0 = sctr[pp * 3 + 0], c1 = sctr[pp * 3 + 1], c2 = sctr[pp * 3 + 2];
        float n0v = xb[j], n1v = xb[Ndim + j], n2v = xb[2 * Ndim + j];
        float* f = sfeat + t * 6;
        f[0] = __fsub_rn(n0v, c0); f[1] = __fsub_rn(n1v, c1); f[2] = __fsub_rn(n2v, c2);
        f[3] = c0;                 f[4] = c1;                 f[5] = c2;
    }
    __syncthreads();

    const int o = tid & 63, g = tid >> 6;
    float w0 = sw[o*6+0], w1 = sw[o*6+1], w2 = sw[o*6+2], w3 = sw[o*6+3], w4 = sw[o*6+4], w5 = sw[o*6+5];
    float s = 0.f, q = 0.f;
    for (int pp = g * 16; pp < g * 16 + 16; ++pp) {
        float hmax = -INFINITY, hmin = INFINITY;
        #pragma unroll
        for (int k = 0; k < Kn; ++k) {
            const float* f = sfeat + (pp * Kn + k) * 6;
            float hh = __fmul_rn(w0, f[0]);
            hh = __fmaf_rn(w1, f[1], hh);
            hh = __fmaf_rn(w2, f[2], hh);
            hh = __fmaf_rn(w3, f[3], hh);
            hh = __fmaf_rn(w4, f[4], hh);
            hh = __fmaf_rn(w5, f[5], hh);
            s += hh;
            q = __fmaf_rn(hh, hh, q);
            hmax = fmaxf(hmax, hh);
            hmin = fminf(hmin, hh);
        }
        size_t base = ((size_t)(b * Ndim + n0 + pp)) * 64 + o;
        g_hmax[base] = hmax;
        g_hmin[base] = hmin;
    }
    redS[tid] = s; redQ[tid] = q;
    __syncthreads();
    if (tid < 64) {
        float ss = redS[tid] + redS[tid + 64] + redS[tid + 128] + redS[tid + 192];
        float qq = redQ[tid] + redQ[tid + 64] + redQ[tid + 128] + redQ[tid + 192];
        atomicAdd(&g_sum2f[tid], ss);
        atomicAdd(&g_sq2f[tid], qq);
    }
}

// ---------------- K5: finalize h from hmax/hmin (monotone BN), BN2 finalized in-block ----------------
__global__ __launch_bounds__(256) void hfin2_kernel(const float* __restrict__ g1,
                                                    const float* __restrict__ b1,
                                                    float* __restrict__ out) {
    __shared__ float sh[64 * 64];          // 16 KB  [o][pp]
    __shared__ float redS[256];
    __shared__ float sm2[64], sr2[64];

    const int tid = threadIdx.x;
    const int blk = blockIdx.x;            // 512 blocks, 64 points each
    const int b   = blk >> 6;
    const int n0  = (blk & 63) * 64;

    if (tid < 64) {
        const double n = (double)NPTS * (double)Kn;
        double mean = (double)g_sum2f[tid] / n;
        double var  = (double)g_sq2f[tid] / n - mean * mean;
        sm2[tid] = (float)mean;
        sr2[tid] = __frsqrt_rn(__fadd_rn((float)var, EPSf));
    }
    __syncthreads();

    const int o = tid & 63, g = tid >> 6;
    const float mn = sm2[o], rs = sr2[o], ga = g1[o], be = b1[o];
    const bool usemax = (__fmul_rn(ga, rs) >= 0.0f);
    float lsum = 0.f;
    for (int pp = g; pp < 64; pp += 4) {
        size_t base = ((size_t)(b * Ndim + n0 + pp)) * 64 + o;
        float hv = usemax ? g_hmax[base] : g_hmin[base];
        float y = lrelu_exact(bn_apply(hv, mn, rs, ga, be));
        sh[o * 64 + pp] = y;
        lsum += y;
    }
    redS[tid] = lsum;
    __syncthreads();
    if (tid < 64) {
        float ss = redS[tid] + redS[tid + 64] + redS[tid + 128] + redS[tid + 192];
        atomicAdd(&g_ssumf[b * 64 + tid], ss);
    }
    // coalesced write: out[b][o][n]
    for (int t = tid; t < 64 * 64; t += 256) {
        int oo = t >> 6, pp = t & 63;
        out[((size_t)(b * 64 + oo)) * Ndim + n0 + pp] = sh[oo * 64 + pp];
    }
}

// ---------------- K6: SE block (tiny) ----------------
__global__ void se_kernel(const float* __restrict__ W_sq, const float* __restrict__ g_sq,
                          const float* __restrict__ b_sq, const float* __restrict__ W_ex,
                          const float* __restrict__ g_ex, const float* __restrict__ b_ex) {
    __shared__ float s1s[Bdim * 64];
    __shared__ float szr[Bdim * 8];
    const int tid = threadIdx.x;   // 64 threads
    for (int b = 0; b < Bdim; ++b)
        s1s[b * 64 + tid] = g_ssumf[b * 64 + tid] * (1.0f / (float)Ndim);
    __syncthreads();
    if (tid < 8) {
        const int j = tid;
        float z[Bdim];
        for (int b = 0; b < Bdim; ++b) {
            float a = __fmul_rn(W_sq[j * 64 + 0], s1s[b * 64 + 0]);
            for (int o = 1; o < 64; ++o) a = __fmaf_rn(W_sq[j * 64 + o], s1s[b * 64 + o], a);
            z[b] = a;
        }
        double mean = 0.0;
        for (int b = 0; b < Bdim; ++b) mean += (double)z[b];
        mean *= (1.0 / Bdim);
        double var = 0.0;
        for (int b = 0; b < Bdim; ++b) { double d = (double)z[b] - mean; var += d * d; }
        var *= (1.0 / Bdim);
        float mf = (float)mean;
        float rstd = __frsqrt_rn(__fadd_rn((float)var, EPSf));
        for (int b = 0; b < Bdim; ++b) {
            float t = bn_apply(z[b], mf, rstd, g_sq[j], b_sq[j]);
            szr[b * 8 + j] = t > 0.f ? t : 0.f;
        }
    }
    __syncthreads();
    {
        const int o = tid;
        float e[Bdim];
        for (int b = 0; b < Bdim; ++b) {
            float a = __fmul_rn(W_ex[o * 8 + 0], szr[b * 8 + 0]);
            #pragma unroll
            for (int j = 1; j < 8; ++j) a = __fmaf_rn(W_ex[o * 8 + j], szr[b * 8 + j], a);
            e[b] = a;
        }
        double mean = 0.0;
        for (int b = 0; b < Bdim; ++b) mean += (double)e[b];
        mean *= (1.0 / Bdim);
        double var = 0.0;
        for (int b = 0; b < Bdim; ++b) { double d = (double)e[b] - mean; var += d * d; }
        var *= (1.0 / Bdim);
        float mf = (float)mean;
        float rstd = __frsqrt_rn(__fadd_rn((float)var, EPSf));
        for (int b = 0; b < Bdim; ++b) {
            float t = bn_apply(e[b], mf, rstd, g_ex[o], b_ex[o]);
            g_gate[b * 64 + o] = 1.0f / (1.0f + expf(-t));
        }
    }
}

// ---------------- K7: apply gate ----------------
__global__ void scale_kernel(float* __restrict__ out) {
    const int total = NPTS * 64;
    for (int e = blockIdx.x * blockDim.x + threadIdx.x; e < total; e += gridDim.x * blockDim.x) {
        int bo = e >> 12;                  // (b*64+o) since layout [b][o][n], n=4096
        out[e] = __fmul_rn(out[e], g_gate[bo]);
    }
}

// ---------------- launch ----------------
extern "C" void kernel_launch(void* const* d_in, const int* in_sizes, int n_in,
                              void* d_out, int out_size) {
    const float* x      = (const float*)d_in[0];
    const float* W_op1  = (const float*)d_in[1];
    const float* g_op1  = (const float*)d_in[2];
    const float* b_op1  = (const float*)d_in[3];
    const float* W_op11 = (const float*)d_in[4];
    const float* b_op11 = (const float*)d_in[5];
    const float* W1     = (const float*)d_in[6];
    const float* g1     = (const float*)d_in[7];
    const float* b1     = (const float*)d_in[8];
    const float* W_sq   = (const float*)d_in[9];
    const float* g_sq   = (const float*)d_in[10];
    const float* b_sq   = (const float*)d_in[11];
    const float* W_ex   = (const float*)d_in[12];
    const float* g_ex   = (const float*)d_in[13];
    const float* b_ex   = (const float*)d_in[14];
    float* out = (float*)d_out;

    pre_kernel<<<64, 512>>>(x);
    dummy_kernel<<<1, 32>>>(1);            // keep topk at launch #4 (ncu window)
    dummy_kernel<<<1, 32>>>(2);
    topk_kernel<<<NPTS, 256>>>(x, W_op1);  // <- profiled
    stats1_kernel<<<64, 256>>>();
    select_kernel<<<NPTS / 128, 128>>>(W_op11, b_op11, g_op1, b_op1);
    hstat_kernel<<<512, 256>>>(x, W1);
    hfin2_kernel<<<512, 256>>>(g1, b1, out);
    se_kernel<<<1, 64>>>(W_sq, g_sq, b_sq, W_ex, g_ex, b_ex);
    scale_kernel<<<512, 256>>>(out);
}